// round 16
// baseline (speedup 1.0000x reference)
#include <cuda_runtime.h>
#include <cstdint>

#define NBH 64
#define L   512
#define DD  64
#define QROWS 32     // q rows per CTA
#define SQP 68       // sQ row pitch (floats)
#define SKP 68       // sK row pitch
#define SPP 132      // sP row pitch
#define SVTP 132     // sVt row pitch

typedef unsigned long long ull;

// Scratch (device globals; no allocation in kernel_launch)
__device__ float g_ksum [NBH * L * DD];   // [bh][j][d]  (natural)
__device__ float g_vsumT[NBH * DD * L];   // [bh][d][j]  (transposed)

__device__ __forceinline__ void ffma2(ull& c, ull a, ull b) {
    asm("fma.rn.f32x2 %0, %1, %2, %0;" : "+l"(c) : "l"(a), "l"(b));
}
__device__ __forceinline__ float2 unpack2(ull x) {
    float2 f;
    asm("mov.b64 {%0, %1}, %2;" : "=f"(f.x), "=f"(f.y) : "l"(x));
    return f;
}

// ---------------------------------------------------------------------------
// K1: reduce r; ksum natural [bh][j][d] (direct), vsumT [bh][d][j] via smem
// transpose. grid (8 jblocks, 64 bh) x 256 threads.
// ---------------------------------------------------------------------------
__global__ __launch_bounds__(256)
void reduce_kv_kernel(const float* __restrict__ k, const float* __restrict__ v) {
    __shared__ float sT[DD * 65];
    const int t  = threadIdx.x;
    const int jb = blockIdx.x;
    const int bh = blockIdx.y;

    #pragma unroll
    for (int p = 0; p < 4; ++p) {
        int f4 = p * 256 + t;
        int jl = f4 >> 4, dq = (f4 & 15) << 2;
        size_t base = (((size_t)bh * L + jb * 64 + jl) * 4) * DD + dq;
        float4 a0 = *(const float4*)(k + base);
        float4 a1 = *(const float4*)(k + base + DD);
        float4 a2 = *(const float4*)(k + base + 2 * DD);
        float4 a3 = *(const float4*)(k + base + 3 * DD);
        float4 ks;
        ks.x = (a0.x + a1.x) + (a2.x + a3.x);
        ks.y = (a0.y + a1.y) + (a2.y + a3.y);
        ks.z = (a0.z + a1.z) + (a2.z + a3.z);
        ks.w = (a0.w + a1.w) + (a2.w + a3.w);
        *(float4*)(g_ksum + ((size_t)bh * L + jb * 64 + jl) * DD + dq) = ks;
        float4 b0 = *(const float4*)(v + base);
        float4 b1 = *(const float4*)(v + base + DD);
        float4 b2 = *(const float4*)(v + base + 2 * DD);
        float4 b3 = *(const float4*)(v + base + 3 * DD);
        sT[(dq + 0) * 65 + jl] = (b0.x + b1.x) + (b2.x + b3.x);
        sT[(dq + 1) * 65 + jl] = (b0.y + b1.y) + (b2.y + b3.y);
        sT[(dq + 2) * 65 + jl] = (b0.z + b1.z) + (b2.z + b3.z);
        sT[(dq + 3) * 65 + jl] = (b0.w + b1.w) + (b2.w + b3.w);
    }
    __syncthreads();
    #pragma unroll
    for (int p = 0; p < 4; ++p) {
        int f4 = p * 256 + t;
        int dl = f4 >> 4, jq = (f4 & 15) << 2;
        float4 o;
        o.x = sT[dl * 65 + jq + 0];
        o.y = sT[dl * 65 + jq + 1];
        o.z = sT[dl * 65 + jq + 2];
        o.w = sT[dl * 65 + jq + 3];
        *(float4*)(g_vsumT + ((size_t)bh * DD + dl) * L + jb * 64 + jq) = o;
    }
}

// ---------------------------------------------------------------------------
// K2 (fused): per CTA 32 q rows of one bh; warp owns 4 rows; lane owns
// cols {l, l+32, l+64, l+96} of each 128-col chunk (QK) and d {l, l+32} (PV).
// Even/odd-split f32x2 accumulators: QK splits over d, PV splits over j.
// All 4 QK chunks: e=exp(u*omega) raw -> attn; Z lane-partials; one shuffle
// reduce; PV per chunk: fixup (L2 re-read * 1/Z -> attn + sP) + sVt tile + MMA.
// smem: QK sQ[32][68]+sK[128][68]=43.5KB ; PV sP[32][132]+sVt[64][132]=50.7KB
// (aliased). launch_bounds(256,4) -> 64-reg target, 4 CTA/SM, 32 warps/SM.
// ---------------------------------------------------------------------------
extern __shared__ float smem[];

__global__ __launch_bounds__(256, 4)
void attn_fused(const float* __restrict__ q,
                const float* __restrict__ omega,
                const int*   __restrict__ mask,
                float* __restrict__ attn,
                float* __restrict__ out_o) {
    float* sQ  = smem;                   // [32][SQP]   (QK)
    float* sK  = smem + QROWS * SQP;     // [128][SKP]  (QK)
    float* sP  = smem;                   // [32][SPP]   (PV, alias)
    float* sVt = smem + QROWS * SPP;     // [64][SVTP]  (PV, alias)

    const int t  = threadIdx.x;
    const int bh = blockIdx.y;
    const int b  = bh >> 3;
    const int qb = blockIdx.x * QROWS;
    const int w  = t >> 5, l = t & 31;

    // fill sQ (fold 1/8): 32 rows x 16 float4 = 512 -> 2 per thread
    #pragma unroll
    for (int p = 0; p < 2; ++p) {
        int f4 = p * 256 + t;
        int r = f4 >> 4, dq = (f4 & 15) << 2;
        float4 qv = *(const float4*)(q + ((size_t)bh * L + qb + r) * DD + dq);
        qv.x *= 0.125f; qv.y *= 0.125f; qv.z *= 0.125f; qv.w *= 0.125f;
        *(float4*)(sQ + r * SQP + dq) = qv;
    }

    float Zp[4];
    #pragma unroll
    for (int r = 0; r < 4; ++r) Zp[r] = 0.f;

    // ---------------- QK: 4 chunks of 128 cols ----------------
    #pragma unroll
    for (int c = 0; c < 4; ++c) {
        __syncthreads();
        // fill sK chunk: 128 rows x 16 float4 = 2048 -> 8 per thread
        #pragma unroll
        for (int p = 0; p < 8; ++p) {
            int f4 = p * 256 + t;
            int row = f4 >> 4, dq = (f4 & 15) << 2;
            *(float4*)(sK + row * SKP + dq) =
                *(const float4*)(g_ksum + ((size_t)bh * L + c * 128 + row) * DD + dq);
        }
        __syncthreads();

        ull acc[4][4];
        #pragma unroll
        for (int r = 0; r < 4; ++r)
            #pragma unroll
            for (int i = 0; i < 4; ++i) acc[r][i] = 0;

        // even/odd-d split: a,b loaded as ulonglong2 (d-pairs), no packing
        #pragma unroll
        for (int h = 0; h < 2; ++h) {         // i-halves to cap live regs
            #pragma unroll 4
            for (int dq = 0; dq < DD; dq += 4) {
                ulonglong2 b0 = *(const ulonglong2*)(sK + (l + 32 * (2 * h + 0)) * SKP + dq);
                ulonglong2 b1 = *(const ulonglong2*)(sK + (l + 32 * (2 * h + 1)) * SKP + dq);
                #pragma unroll
                for (int r = 0; r < 4; ++r) {
                    ulonglong2 a = *(const ulonglong2*)(sQ + (4 * w + r) * SQP + dq);
                    ffma2(acc[r][2 * h + 0], a.x, b0.x);
                    ffma2(acc[r][2 * h + 0], a.y, b0.y);
                    ffma2(acc[r][2 * h + 1], a.x, b1.x);
                    ffma2(acc[r][2 * h + 1], a.y, b1.y);
                }
            }
        }

        // epilogue: u = lo+hi; e = mask ? 0 : exp(u*omega); raw e -> attn
        #pragma unroll
        for (int r = 0; r < 4; ++r) {
            int gi = qb + 4 * w + r;
            size_t obase = ((size_t)b * L + gi) * L + c * 128 + l;
            size_t abase = ((size_t)bh * L + gi) * L + c * 128 + l;
            float es = 0.f;
            #pragma unroll
            for (int i = 0; i < 4; ++i) {
                float2 uh = unpack2(acc[r][i]);
                float u = uh.x + uh.y;
                float om = omega[obase + 32 * i];
                int   mk = mask[obase + 32 * i];
                float e = mk ? 0.f : __expf(u * om);
                attn[abase + 32 * i] = e;
                es += e;
            }
            Zp[r] += es;
        }
    }

    // Z reduction (once, covers all chunks)
    float Zinv[4];
    #pragma unroll
    for (int r = 0; r < 4; ++r) {
        float z = Zp[r];
        #pragma unroll
        for (int o = 16; o > 0; o >>= 1)
            z += __shfl_xor_sync(0xffffffffu, z, o);
        Zinv[r] = 1.0f / z;
    }

    // ---------------- PV: 4 chunks of 128 j ----------------
    ull oacc[4][2];
    #pragma unroll
    for (int r = 0; r < 4; ++r) { oacc[r][0] = 0; oacc[r][1] = 0; }

    #pragma unroll
    for (int c = 0; c < 4; ++c) {
        __syncthreads();   // (c=0: QK reads done before alias; c>0: prev PV done with sVt)
        // fill sVt tile: 64 d-rows x 32 float4 = 2048 -> 8 per thread
        #pragma unroll
        for (int p = 0; p < 8; ++p) {
            int f4 = p * 256 + t;
            int row = f4 >> 5, jq = (f4 & 31) << 2;
            *(float4*)(sVt + row * SVTP + jq) =
                *(const float4*)(g_vsumT + ((size_t)bh * DD + row) * L + c * 128 + jq);
        }
        // fixup: same-thread re-read raw e (L2-hot), *1/Z -> attn + sP (warp-local)
        #pragma unroll
        for (int r = 0; r < 4; ++r) {
            int gi = qb + 4 * w + r;
            size_t abase = ((size_t)bh * L + gi) * L + c * 128 + l;
            float iz = Zinv[r];
            #pragma unroll
            for (int i = 0; i < 4; ++i) {
                float x = attn[abase + 32 * i] * iz;
                attn[abase + 32 * i] = x;
                sP[(4 * w + r) * SPP + l + 32 * i] = x;
            }
        }
        __syncthreads();   // sVt ready (sP is warp-private)

        // even/odd-j split: a (P pairs) and b (Vt pairs) as ulonglong2
        #pragma unroll 4
        for (int jq = 0; jq < 128; jq += 4) {
            ulonglong2 b0 = *(const ulonglong2*)(sVt + l * SVTP + jq);
            ulonglong2 b1 = *(const ulonglong2*)(sVt + (l + 32) * SVTP + jq);
            #pragma unroll
            for (int r = 0; r < 4; ++r) {
                ulonglong2 a = *(const ulonglong2*)(sP + (4 * w + r) * SPP + jq);
                ffma2(oacc[r][0], a.x, b0.x);
                ffma2(oacc[r][0], a.y, b0.y);
                ffma2(oacc[r][1], a.x, b1.x);
                ffma2(oacc[r][1], a.y, b1.y);
            }
        }
    }

    // write O: row = qb+4w+r; lane d = l and l+32 (sum even/odd-j halves)
    #pragma unroll
    for (int r = 0; r < 4; ++r) {
        size_t orow = ((size_t)bh * L + qb + 4 * w + r) * DD;
        float2 d0 = unpack2(oacc[r][0]);
        float2 d1 = unpack2(oacc[r][1]);
        out_o[orow + l]      = d0.x + d0.y;
        out_o[orow + l + 32] = d1.x + d1.y;
    }
}

// ---------------------------------------------------------------------------
extern "C" void kernel_launch(void* const* d_in, const int* in_sizes, int n_in,
                              void* d_out, int out_size) {
    const float* q     = (const float*)d_in[0];
    const float* k     = (const float*)d_in[1];
    const float* v     = (const float*)d_in[2];
    const float* omega = (const float*)d_in[3];
    const int*   mask  = (const int*)d_in[4];

    float* out_o    = (float*)d_out;
    float* out_attn = out_o + (size_t)NBH * L * DD;   // [output | attn]

    const int smem_qk = (QROWS * SQP + 128 * SKP) * (int)sizeof(float);   // 43520
    const int smem_pv = (QROWS * SPP + DD * SVTP) * (int)sizeof(float);   // 50688
    const int smem2 = smem_qk > smem_pv ? smem_qk : smem_pv;
    cudaFuncSetAttribute(attn_fused, cudaFuncAttributeMaxDynamicSharedMemorySize, smem2);

    reduce_kv_kernel<<<dim3(8, NBH), 256>>>(k, v);
    attn_fused<<<dim3(L / QROWS, NBH), 256, smem2>>>(q, omega, mask, out_attn, out_o);
}

// round 17
// speedup vs baseline: 1.3627x; 1.3627x over previous
#include <cuda_runtime.h>
#include <cstdint>

#define NBH 64
#define L   512
#define DD  64
#define SQP 68    // sQ row pad (floats)
#define SKP 260   // sKT row pad (floats)
#define SPP 132   // sP row pitch (PV)
#define SVTP 132  // sVt row pitch (PV)

typedef unsigned long long ull;

// Scratch (device globals; no allocation in kernel_launch)
__device__ float g_ksumT[NBH * DD * L];   // [bh][d][j]  (transposed)
__device__ float g_vsumT[NBH * DD * L];   // [bh][d][j]  (transposed)

__device__ __forceinline__ ull pack2(float x) {
    ull r; unsigned int xi = __float_as_uint(x);
    asm("mov.b64 %0, {%1, %1};" : "=l"(r) : "r"(xi));
    return r;
}
__device__ __forceinline__ ull pack2f(float x, float y) {
    ull r;
    asm("mov.b64 %0, {%1, %2};" : "=l"(r) : "f"(x), "f"(y));
    return r;
}
__device__ __forceinline__ void ffma2(ull& c, ull a, ull b) {
    asm("fma.rn.f32x2 %0, %1, %2, %0;" : "+l"(c) : "l"(a), "l"(b));
}
__device__ __forceinline__ float2 unpack2(ull x) {
    float2 f;
    asm("mov.b64 {%0, %1}, %2;" : "=f"(f.x), "=f"(f.y) : "l"(x));
    return f;
}

// ---------------------------------------------------------------------------
// K1: reduce r; BOTH ksum and vsum written TRANSPOSED [bh][d][j] via two smem
// transpose buffers. grid (8 jblocks, 64 bh) x 256 threads.
// ---------------------------------------------------------------------------
__global__ __launch_bounds__(256)
void reduce_kv_kernel(const float* __restrict__ k, const float* __restrict__ v) {
    __shared__ float sTk[DD * 65];
    __shared__ float sTv[DD * 65];
    const int t  = threadIdx.x;
    const int jb = blockIdx.x;
    const int bh = blockIdx.y;

    #pragma unroll
    for (int p = 0; p < 4; ++p) {
        int f4 = p * 256 + t;
        int jl = f4 >> 4, dq = (f4 & 15) << 2;
        size_t base = (((size_t)bh * L + jb * 64 + jl) * 4) * DD + dq;
        float4 a0 = *(const float4*)(k + base);
        float4 a1 = *(const float4*)(k + base + DD);
        float4 a2 = *(const float4*)(k + base + 2 * DD);
        float4 a3 = *(const float4*)(k + base + 3 * DD);
        sTk[(dq + 0) * 65 + jl] = (a0.x + a1.x) + (a2.x + a3.x);
        sTk[(dq + 1) * 65 + jl] = (a0.y + a1.y) + (a2.y + a3.y);
        sTk[(dq + 2) * 65 + jl] = (a0.z + a1.z) + (a2.z + a3.z);
        sTk[(dq + 3) * 65 + jl] = (a0.w + a1.w) + (a2.w + a3.w);
        float4 b0 = *(const float4*)(v + base);
        float4 b1 = *(const float4*)(v + base + DD);
        float4 b2 = *(const float4*)(v + base + 2 * DD);
        float4 b3 = *(const float4*)(v + base + 3 * DD);
        sTv[(dq + 0) * 65 + jl] = (b0.x + b1.x) + (b2.x + b3.x);
        sTv[(dq + 1) * 65 + jl] = (b0.y + b1.y) + (b2.y + b3.y);
        sTv[(dq + 2) * 65 + jl] = (b0.z + b1.z) + (b2.z + b3.z);
        sTv[(dq + 3) * 65 + jl] = (b0.w + b1.w) + (b2.w + b3.w);
    }
    __syncthreads();
    #pragma unroll
    for (int p = 0; p < 4; ++p) {
        int f4 = p * 256 + t;
        int dl = f4 >> 4, jq = (f4 & 15) << 2;
        size_t gbase = ((size_t)bh * DD + dl) * L + jb * 64 + jq;
        float4 o;
        o.x = sTk[dl * 65 + jq + 0];
        o.y = sTk[dl * 65 + jq + 1];
        o.z = sTk[dl * 65 + jq + 2];
        o.w = sTk[dl * 65 + jq + 3];
        *(float4*)(g_ksumT + gbase) = o;
        float4 u;
        u.x = sTv[dl * 65 + jq + 0];
        u.y = sTv[dl * 65 + jq + 1];
        u.z = sTv[dl * 65 + jq + 2];
        u.w = sTv[dl * 65 + jq + 3];
        *(float4*)(g_vsumT + gbase) = u;
    }
}

// ---------------------------------------------------------------------------
// K2 (fused): per CTA 64 q rows of one bh.
//   QK (R14 layout, unchanged): 2 chunks of 256 cols; c=0 raw e -> attn,
//   c=1 e in regs; one Z shuffle-reduce.
//   Epilogue: chunk1 P (regs*iz) -> attn; chunk0 fixup (L2 re-read*iz) -> attn.
//   PV: 4 subchunks of 128 j; sP restaged from attn (L2-hot), sVt from
//   g_vsumT; even/odd-j ull accumulators -> zero pack MOVs in inner loop.
// smem: QK sQ[64][68]+sKT[64][260]=84KB ; PV sP[64][132]+sVt[64][132]=67.6KB
// (aliased, max 84KB) -> 2 CTA/SM.
// ---------------------------------------------------------------------------
extern __shared__ float smem[];

__global__ __launch_bounds__(256, 2)
void attn_fused(const float* __restrict__ q,
                const float* __restrict__ omega,
                const int*   __restrict__ mask,
                float* __restrict__ attn,
                float* __restrict__ out_o) {
    float* sQ  = smem;              // [64][SQP]  (QK)
    float* sKT = smem + 64 * SQP;   // [64][SKP]  (QK)
    float* sP  = smem;              // [64][SPP]  (PV, alias)
    float* sVt = smem + 64 * SPP;   // [64][SVTP] (PV, alias)

    const int t  = threadIdx.x;
    const int bh = blockIdx.y;
    const int b  = bh >> 3;
    const int qb = blockIdx.x * 64;
    const int w  = t >> 5, l = t & 31;

    // fill sQ (fold 1/8)
    #pragma unroll
    for (int p = 0; p < 4; ++p) {
        int f4 = p * 256 + t;
        int r = f4 >> 4, dq = (f4 & 15) << 2;
        float4 qv = *(const float4*)(q + ((size_t)bh * L + qb + r) * DD + dq);
        qv.x *= 0.125f; qv.y *= 0.125f; qv.z *= 0.125f; qv.w *= 0.125f;
        *(float4*)(sQ + r * SQP + dq) = qv;
    }

    float Zp[8], Zinv[8];
    #pragma unroll
    for (int r = 0; r < 8; ++r) Zp[r] = 0.f;

    ull acc[8][4];

    #pragma unroll
    for (int c = 0; c < 2; ++c) {
        __syncthreads();
        // fill sKT chunk c
        #pragma unroll
        for (int p = 0; p < 16; ++p) {
            int f4 = p * 256 + t;
            int d = f4 >> 6, cq = (f4 & 63) << 2;
            *(float4*)(sKT + d * SKP + cq) =
                *(const float4*)(g_ksumT + ((size_t)bh * DD + d) * L + c * 256 + cq);
        }
        __syncthreads();

        #pragma unroll
        for (int r = 0; r < 8; ++r)
            #pragma unroll
            for (int i = 0; i < 4; ++i) acc[r][i] = 0;

        const float* bp = sKT + 4 * l;
        #pragma unroll 2
        for (int d = 0; d < DD; d += 2) {
            float2 a[8];
            #pragma unroll
            for (int r = 0; r < 8; ++r)
                a[r] = *(const float2*)(sQ + (8 * w + r) * SQP + d);
            #pragma unroll
            for (int dd = 0; dd < 2; ++dd) {
                ulonglong2 b0 = *(const ulonglong2*)(bp + (d + dd) * SKP);
                ulonglong2 b1 = *(const ulonglong2*)(bp + (d + dd) * SKP + 128);
                #pragma unroll
                for (int r = 0; r < 8; ++r) {
                    ull ar = pack2(dd ? a[r].y : a[r].x);
                    ffma2(acc[r][0], ar, b0.x);
                    ffma2(acc[r][1], ar, b0.y);
                    ffma2(acc[r][2], ar, b1.x);
                    ffma2(acc[r][3], ar, b1.y);
                }
            }
        }

        // epilogue: e = mask ? 0 : exp(u*omega); lane-partial Z
        #pragma unroll
        for (int r = 0; r < 8; ++r) {
            int gi = qb + 8 * w + r;
            size_t orow = ((size_t)b * L + gi) * L + c * 256;
            float4 o0 = *(const float4*)(omega + orow + 4 * l);
            float4 o1 = *(const float4*)(omega + orow + 128 + 4 * l);
            int4 m0 = *(const int4*)(mask + orow + 4 * l);
            int4 m1 = *(const int4*)(mask + orow + 128 + 4 * l);
            float2 u0 = unpack2(acc[r][0]), u1 = unpack2(acc[r][1]);
            float2 u2 = unpack2(acc[r][2]), u3 = unpack2(acc[r][3]);
            float e0 = m0.x ? 0.f : __expf(u0.x * o0.x);
            float e1 = m0.y ? 0.f : __expf(u0.y * o0.y);
            float e2 = m0.z ? 0.f : __expf(u1.x * o0.z);
            float e3 = m0.w ? 0.f : __expf(u1.y * o0.w);
            float e4 = m1.x ? 0.f : __expf(u2.x * o1.x);
            float e5 = m1.y ? 0.f : __expf(u2.y * o1.y);
            float e6 = m1.z ? 0.f : __expf(u3.x * o1.z);
            float e7 = m1.w ? 0.f : __expf(u3.y * o1.w);
            Zp[r] += ((e0 + e1) + (e2 + e3)) + ((e4 + e5) + (e6 + e7));
            if (c == 0) {
                size_t arow = ((size_t)bh * L + gi) * L;
                *(float4*)(attn + arow + 4 * l)       = make_float4(e0, e1, e2, e3);
                *(float4*)(attn + arow + 128 + 4 * l) = make_float4(e4, e5, e6, e7);
            } else {
                acc[r][0] = pack2f(e0, e1);
                acc[r][1] = pack2f(e2, e3);
                acc[r][2] = pack2f(e4, e5);
                acc[r][3] = pack2f(e6, e7);
            }
        }
    }

    // Z reduction across lanes (covers both chunks)
    #pragma unroll
    for (int r = 0; r < 8; ++r) {
        float z = Zp[r];
        #pragma unroll
        for (int o = 16; o > 0; o >>= 1)
            z += __shfl_xor_sync(0xffffffffu, z, o);
        Zinv[r] = 1.0f / z;
    }

    // chunk1 P (regs * iz) -> attn ; acc dies here
    #pragma unroll
    for (int r = 0; r < 8; ++r) {
        int gi = qb + 8 * w + r;
        float iz = Zinv[r];
        float2 e0 = unpack2(acc[r][0]), e1 = unpack2(acc[r][1]);
        float2 e2 = unpack2(acc[r][2]), e3 = unpack2(acc[r][3]);
        size_t arow = ((size_t)bh * L + gi) * L + 256;
        *(float4*)(attn + arow + 4 * l) =
            make_float4(e0.x * iz, e0.y * iz, e1.x * iz, e1.y * iz);
        *(float4*)(attn + arow + 128 + 4 * l) =
            make_float4(e2.x * iz, e2.y * iz, e3.x * iz, e3.y * iz);
    }
    // chunk0 fixup: same-thread re-read raw e (L2-hot), * iz -> attn
    #pragma unroll
    for (int r = 0; r < 8; ++r) {
        int gi = qb + 8 * w + r;
        size_t arow = ((size_t)bh * L + gi) * L;
        float4 x0 = *(const float4*)(attn + arow + 4 * l);
        float4 x1 = *(const float4*)(attn + arow + 128 + 4 * l);
        float iz = Zinv[r];
        x0.x *= iz; x0.y *= iz; x0.z *= iz; x0.w *= iz;
        x1.x *= iz; x1.y *= iz; x1.z *= iz; x1.w *= iz;
        *(float4*)(attn + arow + 4 * l)       = x0;
        *(float4*)(attn + arow + 128 + 4 * l) = x1;
    }

    // ------------------- PV: 4 subchunks of 128 j -------------------
    const float* vtbase = g_vsumT + (size_t)bh * DD * L;
    ull oacc[8][2];
    #pragma unroll
    for (int r = 0; r < 8; ++r) { oacc[r][0] = 0; oacc[r][1] = 0; }

    #pragma unroll
    for (int c = 0; c < 4; ++c) {
        __syncthreads();   // prior MMA done with sP/sVt (c=0: QK/epi done; attn visible)
        // fill sVt: 64 d-rows x 128 j  (2048 float4 -> 8/thread)
        #pragma unroll
        for (int p = 0; p < 8; ++p) {
            int f4 = p * 256 + t;
            int row = f4 >> 5, jq = (f4 & 31) << 2;
            *(float4*)(sVt + row * SVTP + jq) =
                *(const float4*)(vtbase + (size_t)row * L + c * 128 + jq);
        }
        // fill sP from attn (L2-hot): 64 rows x 128 j
        #pragma unroll
        for (int p = 0; p < 8; ++p) {
            int f4 = p * 256 + t;
            int row = f4 >> 5, jq = (f4 & 31) << 2;
            *(float4*)(sP + row * SPP + jq) =
                *(const float4*)(attn + ((size_t)bh * L + qb + row) * L + c * 128 + jq);
        }
        __syncthreads();   // tiles ready

        // even/odd-j accumulators: zero pack MOVs
        #pragma unroll 4
        for (int jq = 0; jq < 128; jq += 4) {
            ulonglong2 blo = *(const ulonglong2*)(sVt + l * SVTP + jq);
            ulonglong2 bhi = *(const ulonglong2*)(sVt + (l + 32) * SVTP + jq);
            #pragma unroll
            for (int r = 0; r < 8; ++r) {
                ulonglong2 a = *(const ulonglong2*)(sP + (8 * w + r) * SPP + jq);
                ffma2(oacc[r][0], a.x, blo.x);
                ffma2(oacc[r][0], a.y, blo.y);
                ffma2(oacc[r][1], a.x, bhi.x);
                ffma2(oacc[r][1], a.y, bhi.y);
            }
        }
    }

    // write O: row = qb+8w+r; lane d = l and l+32 (sum even/odd-j halves)
    #pragma unroll
    for (int r = 0; r < 8; ++r) {
        size_t orow = ((size_t)bh * L + qb + 8 * w + r) * DD;
        float2 d0 = unpack2(oacc[r][0]);
        float2 d1 = unpack2(oacc[r][1]);
        out_o[orow + l]      = d0.x + d0.y;
        out_o[orow + l + 32] = d1.x + d1.y;
    }
}

// ---------------------------------------------------------------------------
extern "C" void kernel_launch(void* const* d_in, const int* in_sizes, int n_in,
                              void* d_out, int out_size) {
    const float* q     = (const float*)d_in[0];
    const float* k     = (const float*)d_in[1];
    const float* v     = (const float*)d_in[2];
    const float* omega = (const float*)d_in[3];
    const int*   mask  = (const int*)d_in[4];

    float* out_o    = (float*)d_out;
    float* out_attn = out_o + (size_t)NBH * L * DD;   // [output | attn]

    const int smem_qk = (64 * SQP + 64 * SKP) * (int)sizeof(float);   // 83968
    const int smem_pv = (64 * SPP + 64 * SVTP) * (int)sizeof(float);  // 67584
    const int smem2 = smem_qk > smem_pv ? smem_qk : smem_pv;
    cudaFuncSetAttribute(attn_fused, cudaFuncAttributeMaxDynamicSharedMemorySize, smem2);

    reduce_kv_kernel<<<dim3(8, NBH), 256>>>(k, v);
    attn_fused<<<dim3(8, NBH), 256, smem2>>>(q, omega, mask, out_attn, out_o);
}